// round 16
// baseline (speedup 1.0000x reference)
#include <cuda_runtime.h>
#include <cuda_fp16.h>
#include <cstdint>

#define B_DIM 256
#define D_DIM 65536
#define N_DIM 41
#define G_DIM 2048
#define KSPL  512         // gemm1 K per split (4 splits)
#define NKS   4
#define O_DIM 256
#define E_DIM 512
#define NO_DIM (N_DIM * O_DIM)
#define NSPL2 37          // gemm2 k-splits (296 CTAs = one perfect wave at occ 2)
#define NEG_SLOPE 0.2f

// statics ~73 MB
__device__ unsigned short g_xT[(size_t)D_DIM * B_DIM];          // 32 MB fp16 bits
__device__ unsigned short g_Hp[(size_t)NKS * B_DIM * NO_DIM];   // 21.5 MB fp16 partials
__device__ float g_P[(size_t)NSPL2 * B_DIM * E_DIM];            // 19.4 MB

// ---------------------------------------------------------------- helpers
__device__ __forceinline__ uint32_t sptr(const void* p) {
    return (uint32_t)__cvta_generic_to_shared(p);
}
__device__ __forceinline__ void ldsm4t(uint32_t* r, uint32_t a) {
    asm volatile("ldmatrix.sync.aligned.m8n8.x4.trans.shared.b16 {%0,%1,%2,%3},[%4];"
                 : "=r"(r[0]), "=r"(r[1]), "=r"(r[2]), "=r"(r[3]) : "r"(a));
}
__device__ __forceinline__ void ldsm4(uint32_t* r, uint32_t a) {
    asm volatile("ldmatrix.sync.aligned.m8n8.x4.shared.b16 {%0,%1,%2,%3},[%4];"
                 : "=r"(r[0]), "=r"(r[1]), "=r"(r[2]), "=r"(r[3]) : "r"(a));
}
__device__ __forceinline__ void mma16816h(float* c, const uint32_t* a, const uint32_t* b) {
    asm volatile("mma.sync.aligned.m16n8k16.row.col.f32.f16.f16.f32 "
                 "{%0,%1,%2,%3},{%4,%5,%6,%7},{%8,%9},{%0,%1,%2,%3};"
                 : "+f"(c[0]), "+f"(c[1]), "+f"(c[2]), "+f"(c[3])
                 : "r"(a[0]), "r"(a[1]), "r"(a[2]), "r"(a[3]), "r"(b[0]), "r"(b[1]));
}
__device__ __forceinline__ uint32_t pack2h(float a, float b) {
    return (uint32_t)__half_as_ushort(__float2half_rn(a)) |
           ((uint32_t)__half_as_ushort(__float2half_rn(b)) << 16);
}
// fp32-accurate combine of 4 fp16x2 values -> fp16x2
__device__ __forceinline__ uint32_t comb4(uint32_t a, uint32_t b, uint32_t c, uint32_t d) {
    float2 fa = __half22float2(*(__half2*)&a);
    float2 fb = __half22float2(*(__half2*)&b);
    float2 fc = __half22float2(*(__half2*)&c);
    float2 fd = __half22float2(*(__half2*)&d);
    return pack2h(fa.x + fb.x + fc.x + fd.x, fa.y + fb.y + fc.y + fd.y);
}

// ---------------------------------------------------------------- transpose x -> fp16 xT [D][B]
__global__ __launch_bounds__(256) void transpose_kernel(const float* __restrict__ x) {
    __shared__ float tile[64][65];
    int d0 = blockIdx.x * 64, b0 = blockIdx.y * 64;
    int t = threadIdx.x;
    int br = t / 16, dc = (t % 16) * 4;
#pragma unroll
    for (int p = 0; p < 4; p++) {
        int b = br + p * 16;
        float4 v = *(const float4*)&x[(size_t)(b0 + b) * D_DIM + d0 + dc];
        tile[b][dc] = v.x; tile[b][dc+1] = v.y; tile[b][dc+2] = v.z; tile[b][dc+3] = v.w;
    }
    __syncthreads();
    int dr = t / 16, bc = (t % 16) * 4;
#pragma unroll
    for (int p = 0; p < 4; p++) {
        int d = dr + p * 16;
        size_t off = (size_t)(d0 + d) * B_DIM + b0 + bc;
        *(uint2*)&g_xT[off] = make_uint2(pack2h(tile[bc][d],   tile[bc+1][d]),
                                         pack2h(tile[bc+2][d], tile[bc+3][d]));
    }
}

// ---------------------------------------------------------------- GEMM1 (fp16, tile 128x64, BK=32, prefetch-2, occ 2, K-split 4)
__global__ __launch_bounds__(256, 2) void gemm1_kernel(
    const int* __restrict__ gidx, const float* __restrict__ W, const float* __restrict__ bias)
{
    __shared__ unsigned short sIdx[KSPL];                       // 1 KB
    __shared__ alignas(16) unsigned short As[2][32][136];       // 17.4 KB
    __shared__ alignas(16) unsigned short Bs[2][32][72];        // 9.2 KB

    const int zz    = blockIdx.z;
    const int n     = zz >> 2;
    const int ks    = zz & 3;
    const int kbeg  = ks * KSPL;
    const int bbase = blockIdx.x * 128;
    const int obase = blockIdx.y * 64;
    const int tid = threadIdx.x, lane = tid & 31, warp = tid >> 5;
    const int wm = (warp & 1) * 64, wn = (warp >> 1) * 16;
    const int arow = tid >> 3, acol = (tid & 7) * 8;
    const int brow = tid >> 3, bcol = (tid & 7) * 4;

    for (int i = tid; i < KSPL; i += 256)
        sIdx[i] = (unsigned short)gidx[(size_t)n * G_DIM + kbeg + i];
    __syncthreads();

    const float* Wn = W + (size_t)n * G_DIM * O_DIM + (size_t)kbeg * O_DIM;
    unsigned short* Hdst = g_Hp + (size_t)ks * B_DIM * NO_DIM;
    const int g8 = lane >> 3, i8 = lane & 7;
    const int a_krow = (g8 >> 1) * 8 + i8, a_mcol = (g8 & 1) * 8;
    const int b_krow = (g8 & 1) * 8 + i8, b_ncol = (g8 >> 1) * 8;

    float acc[4][2][4];
#pragma unroll
    for (int i = 0; i < 4; i++)
#pragma unroll
        for (int j = 0; j < 2; j++)
#pragma unroll
            for (int q = 0; q < 4; q++) acc[i][j][q] = 0.0f;

    auto ldg = [&](int ch, uint4& a0, uint4& a1, float4& w0, float4& w1) {
        int k0 = ch * 32;
        int gi = sIdx[k0 + arow];
        const unsigned short* xr = &g_xT[(size_t)gi * B_DIM + bbase + acol];
        a0 = *(const uint4*)xr;
        a1 = *(const uint4*)(xr + 64);
        const float* wr = &Wn[(size_t)(k0 + brow) * O_DIM + obase + bcol];
        w0 = *(const float4*)wr;
        w1 = *(const float4*)(wr + 32);
    };
    auto sts = [&](int buf, uint4 a0, uint4 a1, float4 w0, float4 w1) {
        *(uint4*)&As[buf][arow][acol]      = a0;
        *(uint4*)&As[buf][arow][acol + 64] = a1;
        *(uint2*)&Bs[buf][brow][bcol]      = make_uint2(pack2h(w0.x, w0.y), pack2h(w0.z, w0.w));
        *(uint2*)&Bs[buf][brow][bcol + 32] = make_uint2(pack2h(w1.x, w1.y), pack2h(w1.z, w1.w));
    };
    auto compute = [&](int buf) {
#pragma unroll
        for (int ksb = 0; ksb < 2; ksb++) {
            uint32_t af[4][4], bf[4];
#pragma unroll
            for (int mt = 0; mt < 4; mt++)
                ldsm4t(af[mt], sptr(&As[buf][ksb * 16 + a_krow][wm + mt * 16 + a_mcol]));
            ldsm4t(bf, sptr(&Bs[buf][ksb * 16 + b_krow][wn + b_ncol]));
#pragma unroll
            for (int mt = 0; mt < 4; mt++)
#pragma unroll
                for (int nt = 0; nt < 2; nt++)
                    mma16816h(acc[mt][nt], af[mt], &bf[nt * 2]);
        }
    };

    uint4 A00, A01, A10, A11;
    float4 W00, W01, W10, W11;
    ldg(0, A00, A01, W00, W01);
    sts(0, A00, A01, W00, W01);
    ldg(1, A00, A01, W00, W01);
    __syncthreads();

    const int NCHUNK = KSPL / 32;  // 16
    for (int ch = 0; ch < NCHUNK; ch += 2) {
        if (ch + 2 < NCHUNK) ldg(ch + 2, A10, A11, W10, W11);
        compute(0);
        sts(1, A00, A01, W00, W01);
        __syncthreads();
        if (ch + 3 < NCHUNK) ldg(ch + 3, A00, A01, W00, W01);
        compute(1);
        if (ch + 2 < NCHUNK) sts(0, A10, A11, W10, W11);
        __syncthreads();
    }

    // epilogue: Hp -> fp16, row-major [B][NO]; bias only in split 0
    const int r = lane >> 2, c = (lane & 3) * 2;
#pragma unroll
    for (int mt = 0; mt < 4; mt++)
#pragma unroll
        for (int nt = 0; nt < 2; nt++) {
            int ocol = obase + wn + nt * 8 + c;
            float bv0 = ks ? 0.0f : bias[n * O_DIM + ocol];
            float bv1 = ks ? 0.0f : bias[n * O_DIM + ocol + 1];
            int b0 = bbase + wm + mt * 16 + r;
#pragma unroll
            for (int q = 0; q < 2; q++) {
                size_t base = (size_t)(b0 + q*8) * NO_DIM + (size_t)n * O_DIM + ocol;
                *(uint32_t*)&Hdst[base] =
                    pack2h(acc[mt][nt][q*2] + bv0, acc[mt][nt][q*2+1] + bv1);
            }
        }
}

// ---------------------------------------------------------------- GEMM2 (fp16, BK=16, prefetch-2, occ 2, 37 balanced K-splits)
__global__ __launch_bounds__(256, 2) void gemm2_kernel(const float* __restrict__ W3)
{
    __shared__ alignas(16) unsigned short As[2][128][24];   // 12 KB
    __shared__ alignas(16) unsigned short Bs[2][16][136];   // 8.5 KB

    const int s = blockIdx.z, bbase = blockIdx.x * 128, ebase = blockIdx.y * 128;
    const int pair0  = (s < 32) ? 9 * s : 8 * s + 32;
    const int npairs = (s < 32) ? 9 : 8;
    const int kbeg   = pair0 * 32;
    const int NCHUNK = npairs * 2;            // 18 or 16 (even)

    const int tid = threadIdx.x, lane = tid & 31, warp = tid >> 5;
    const int wm = (warp & 1) * 64, wn = (warp >> 1) * 32;
    const int arow = tid >> 1, ahalf = (tid & 1) * 8;
    const int kkB = tid >> 5, colB = (tid & 31) * 4;
    const int g8 = lane >> 3, i8 = lane & 7;
    const int a_mrow = (g8 & 1) * 8 + i8, a_kcol = (g8 >> 1) * 8;
    const int b_krow = (g8 & 1) * 8 + i8, b_ncol = (g8 >> 1) * 8;

    const size_t HSTRIDE = (size_t)B_DIM * NO_DIM;

    float acc[4][4][4];
#pragma unroll
    for (int i = 0; i < 4; i++)
#pragma unroll
        for (int j = 0; j < 4; j++)
#pragma unroll
            for (int q = 0; q < 4; q++) acc[i][j][q] = 0.0f;

    auto ldg = [&](int ch, uint4* a, float4& p0, float4& p1) {
        int k0 = kbeg + ch * 16;
        size_t off = (size_t)(bbase + arow) * NO_DIM + k0 + ahalf;
#pragma unroll
        for (int q = 0; q < 4; q++)
            a[q] = *(const uint4*)&g_Hp[off + q * HSTRIDE];
        p0 = *(const float4*)&W3[(size_t)(k0 + kkB) * E_DIM + ebase + colB];
        p1 = *(const float4*)&W3[(size_t)(k0 + kkB + 8) * E_DIM + ebase + colB];
    };
    auto sts = [&](int buf, const uint4* a, float4 p0, float4 p1) {
        uint4 c;
        c.x = comb4(a[0].x, a[1].x, a[2].x, a[3].x);
        c.y = comb4(a[0].y, a[1].y, a[2].y, a[3].y);
        c.z = comb4(a[0].z, a[1].z, a[2].z, a[3].z);
        c.w = comb4(a[0].w, a[1].w, a[2].w, a[3].w);
        *(uint4*)&As[buf][arow][ahalf] = c;
        *(uint2*)&Bs[buf][kkB][colB]     = make_uint2(pack2h(p0.x, p0.y), pack2h(p0.z, p0.w));
        *(uint2*)&Bs[buf][kkB + 8][colB] = make_uint2(pack2h(p1.x, p1.y), pack2h(p1.z, p1.w));
    };
    auto compute = [&](int buf) {
        uint32_t af[4][4], bfv[2][4];
#pragma unroll
        for (int mt = 0; mt < 4; mt++)
            ldsm4(af[mt], sptr(&As[buf][wm + mt * 16 + a_mrow][a_kcol]));
#pragma unroll
        for (int np = 0; np < 2; np++)
            ldsm4t(bfv[np], sptr(&Bs[buf][b_krow][wn + np * 16 + b_ncol]));
#pragma unroll
        for (int mt = 0; mt < 4; mt++)
#pragma unroll
            for (int nt = 0; nt < 4; nt++)
                mma16816h(acc[mt][nt], af[mt], &bfv[nt >> 1][(nt & 1) * 2]);
    };

    uint4 A0[4], A1[4];
    float4 B00, B01, B10, B11;
    ldg(0, A0, B00, B01);
    sts(0, A0, B00, B01);
    ldg(1, A0, B00, B01);
    __syncthreads();

    for (int ch = 0; ch < NCHUNK; ch += 2) {
        if (ch + 2 < NCHUNK) ldg(ch + 2, A1, B10, B11);
        compute(0);
        sts(1, A0, B00, B01);
        __syncthreads();
        if (ch + 3 < NCHUNK) ldg(ch + 3, A1 == A0 ? A1 : A0, B00, B01);  // reload into A0
        compute(1);
        if (ch + 2 < NCHUNK) sts(0, A1, B10, B11);
        __syncthreads();
    }

    float* Ps = g_P + (size_t)s * B_DIM * E_DIM;
    const int r = lane >> 2, c = (lane & 3) * 2;
#pragma unroll
    for (int mt = 0; mt < 4; mt++)
#pragma unroll
        for (int nt = 0; nt < 4; nt++) {
            int ecol = ebase + wn + nt * 8 + c;
            int b0 = bbase + wm + mt * 16 + r;
            *(float2*)&Ps[(size_t)b0 * E_DIM + ecol] = make_float2(acc[mt][nt][0], acc[mt][nt][1]);
            *(float2*)&Ps[(size_t)(b0 + 8) * E_DIM + ecol] = make_float2(acc[mt][nt][2], acc[mt][nt][3]);
        }
}

// ---------------------------------------------------------------- reduce (float2 + dual accumulators)
__global__ __launch_bounds__(256) void reduce_kernel(const float* __restrict__ b3, float* __restrict__ out) {
    int i2 = blockIdx.x * 256 + threadIdx.x;      // 0..65535 float2s
    int e2 = i2 & (E_DIM / 2 - 1);
    float2 bv = ((const float2*)b3)[e2];
    float2 s0 = make_float2(bv.x, bv.y);
    float2 s1 = make_float2(0.f, 0.f);
    const float2* P2 = (const float2*)g_P;
    const size_t stride = (size_t)(B_DIM * E_DIM / 2);
#pragma unroll
    for (int s = 0; s < NSPL2 - 1; s += 2) {
        float2 p0 = P2[(size_t)s * stride + i2];
        float2 p1 = P2[(size_t)(s + 1) * stride + i2];
        s0.x += p0.x; s0.y += p0.y;
        s1.x += p1.x; s1.y += p1.y;
    }
    {
        float2 p = P2[(size_t)(NSPL2 - 1) * stride + i2];
        s0.x += p.x; s0.y += p.y;
    }
    float rx = s0.x + s1.x, ry = s0.y + s1.y;
    rx = (rx >= 0.f) ? rx : NEG_SLOPE * rx;
    ry = (ry >= 0.f) ? ry : NEG_SLOPE * ry;
    ((float2*)out)[i2] = make_float2(rx, ry);
}

// ----------------------------------------------------------------
extern "C" void kernel_launch(void* const* d_in, const int* in_sizes, int n_in,
                              void* d_out, int out_size) {
    const float* x    = (const float*)d_in[0];
    const int*   gidx = (const int*)  d_in[1];
    const float* W    = (const float*)d_in[2];
    const float* bias = (const float*)d_in[3];
    const float* W3   = (const float*)d_in[4];
    const float* b3   = (const float*)d_in[5];
    float* out = (float*)d_out;

    {
        dim3 grid(D_DIM / 64, B_DIM / 64);
        transpose_kernel<<<grid, 256>>>(x);
    }
    {
        dim3 grid(B_DIM / 128, O_DIM / 64, N_DIM * NKS);  // (2,4,164) = 1312 CTAs
        gemm1_kernel<<<grid, 256>>>(gidx, W, bias);
    }
    {
        dim3 grid(B_DIM / 128, E_DIM / 128, NSPL2);       // (2,4,37) = 296 CTAs = 1 wave
        gemm2_kernel<<<grid, 256>>>(W3);
    }
    {
        reduce_kernel<<<(B_DIM * E_DIM / 2) / 256, 256>>>(b3, out);  // 256 blocks
    }
}

// round 17
// speedup vs baseline: 1.0572x; 1.0572x over previous
#include <cuda_runtime.h>
#include <cuda_fp16.h>
#include <cstdint>

#define B_DIM 256
#define D_DIM 65536
#define N_DIM 41
#define G_DIM 2048
#define KSPL  1024        // gemm1 K per split
#define O_DIM 256
#define E_DIM 512
#define NO_DIM (N_DIM * O_DIM)
#define NSPL2 37          // gemm2 k-splits (296 CTAs = one perfect wave at occ 2)
#define NEG_SLOPE 0.2f

// statics ~62 MB
__device__ unsigned short g_xT[(size_t)D_DIM * B_DIM];     // 32 MB fp16 bits
__device__ unsigned short g_H0[(size_t)B_DIM * NO_DIM];    // 5.4 MB fp16 partial (k 0..1023)
__device__ unsigned short g_H1[(size_t)B_DIM * NO_DIM];    // 5.4 MB fp16 partial (k 1024..2047)
__device__ float g_P[(size_t)NSPL2 * B_DIM * E_DIM];       // 19.4 MB

// ---------------------------------------------------------------- helpers
__device__ __forceinline__ uint32_t sptr(const void* p) {
    return (uint32_t)__cvta_generic_to_shared(p);
}
__device__ __forceinline__ void ldsm4t(uint32_t* r, uint32_t a) {
    asm volatile("ldmatrix.sync.aligned.m8n8.x4.trans.shared.b16 {%0,%1,%2,%3},[%4];"
                 : "=r"(r[0]), "=r"(r[1]), "=r"(r[2]), "=r"(r[3]) : "r"(a));
}
__device__ __forceinline__ void ldsm4(uint32_t* r, uint32_t a) {
    asm volatile("ldmatrix.sync.aligned.m8n8.x4.shared.b16 {%0,%1,%2,%3},[%4];"
                 : "=r"(r[0]), "=r"(r[1]), "=r"(r[2]), "=r"(r[3]) : "r"(a));
}
__device__ __forceinline__ void mma16816h(float* c, const uint32_t* a, const uint32_t* b) {
    asm volatile("mma.sync.aligned.m16n8k16.row.col.f32.f16.f16.f32 "
                 "{%0,%1,%2,%3},{%4,%5,%6,%7},{%8,%9},{%0,%1,%2,%3};"
                 : "+f"(c[0]), "+f"(c[1]), "+f"(c[2]), "+f"(c[3])
                 : "r"(a[0]), "r"(a[1]), "r"(a[2]), "r"(a[3]), "r"(b[0]), "r"(b[1]));
}
__device__ __forceinline__ uint32_t pack2h(float a, float b) {
    return (uint32_t)__half_as_ushort(__float2half_rn(a)) |
           ((uint32_t)__half_as_ushort(__float2half_rn(b)) << 16);
}
__device__ __forceinline__ uint32_t h2add(uint32_t a, uint32_t b) {
    __half2 r = __hadd2(*(__half2*)&a, *(__half2*)&b);
    return *(uint32_t*)&r;
}

// ---------------------------------------------------------------- transpose x -> fp16 xT [D][B]
__global__ __launch_bounds__(256) void transpose_kernel(const float* __restrict__ x) {
    __shared__ float tile[64][65];
    int d0 = blockIdx.x * 64, b0 = blockIdx.y * 64;
    int t = threadIdx.x;
    int br = t / 16, dc = (t % 16) * 4;
#pragma unroll
    for (int p = 0; p < 4; p++) {
        int b = br + p * 16;
        float4 v = *(const float4*)&x[(size_t)(b0 + b) * D_DIM + d0 + dc];
        tile[b][dc] = v.x; tile[b][dc+1] = v.y; tile[b][dc+2] = v.z; tile[b][dc+3] = v.w;
    }
    __syncthreads();
    int dr = t / 16, bc = (t % 16) * 4;
#pragma unroll
    for (int p = 0; p < 4; p++) {
        int d = dr + p * 16;
        size_t off = (size_t)(d0 + d) * B_DIM + b0 + bc;
        *(uint2*)&g_xT[off] = make_uint2(pack2h(tile[bc][d],   tile[bc+1][d]),
                                         pack2h(tile[bc+2][d], tile[bc+3][d]));
    }
}

// ---------------------------------------------------------------- GEMM1 (fp16, tile 128x64, BK=32, prefetch-2, occ 2, K-split 2)
__global__ __launch_bounds__(256, 2) void gemm1_kernel(
    const int* __restrict__ gidx, const float* __restrict__ W, const float* __restrict__ bias)
{
    __shared__ unsigned short sIdx[KSPL];                       // 2 KB
    __shared__ alignas(16) unsigned short As[2][32][136];       // 17.4 KB
    __shared__ alignas(16) unsigned short Bs[2][32][72];        // 9.2 KB

    const int zz    = blockIdx.z;
    const int n     = zz >> 1;
    const int ks    = zz & 1;
    const int kbeg  = ks * KSPL;
    const int bbase = blockIdx.x * 128;
    const int obase = blockIdx.y * 64;
    const int tid = threadIdx.x, lane = tid & 31, warp = tid >> 5;
    const int wm = (warp & 1) * 64, wn = (warp >> 1) * 16;
    const int arow = tid >> 3, acol = (tid & 7) * 8;
    const int brow = tid >> 3, bcol = (tid & 7) * 4;

    for (int i = tid; i < KSPL; i += 256)
        sIdx[i] = (unsigned short)gidx[(size_t)n * G_DIM + kbeg + i];
    __syncthreads();

    const float* Wn = W + (size_t)n * G_DIM * O_DIM + (size_t)kbeg * O_DIM;
    unsigned short* Hdst = ks ? g_H1 : g_H0;
    const int g8 = lane >> 3, i8 = lane & 7;
    const int a_krow = (g8 >> 1) * 8 + i8, a_mcol = (g8 & 1) * 8;
    const int b_krow = (g8 & 1) * 8 + i8, b_ncol = (g8 >> 1) * 8;

    float acc[4][2][4];
#pragma unroll
    for (int i = 0; i < 4; i++)
#pragma unroll
        for (int j = 0; j < 2; j++)
#pragma unroll
            for (int q = 0; q < 4; q++) acc[i][j][q] = 0.0f;

    auto ldg = [&](int ch, uint4& a0, uint4& a1, float4& w0, float4& w1) {
        int k0 = ch * 32;
        int gi = sIdx[k0 + arow];
        const unsigned short* xr = &g_xT[(size_t)gi * B_DIM + bbase + acol];
        a0 = *(const uint4*)xr;
        a1 = *(const uint4*)(xr + 64);
        const float* wr = &Wn[(size_t)(k0 + brow) * O_DIM + obase + bcol];
        w0 = *(const float4*)wr;
        w1 = *(const float4*)(wr + 32);
    };
    auto sts = [&](int buf, uint4 a0, uint4 a1, float4 w0, float4 w1) {
        *(uint4*)&As[buf][arow][acol]      = a0;
        *(uint4*)&As[buf][arow][acol + 64] = a1;
        *(uint2*)&Bs[buf][brow][bcol]      = make_uint2(pack2h(w0.x, w0.y), pack2h(w0.z, w0.w));
        *(uint2*)&Bs[buf][brow][bcol + 32] = make_uint2(pack2h(w1.x, w1.y), pack2h(w1.z, w1.w));
    };
    auto compute = [&](int buf) {
#pragma unroll
        for (int ksb = 0; ksb < 2; ksb++) {
            uint32_t af[4][4], bf[4];
#pragma unroll
            for (int mt = 0; mt < 4; mt++)
                ldsm4t(af[mt], sptr(&As[buf][ksb * 16 + a_krow][wm + mt * 16 + a_mcol]));
            ldsm4t(bf, sptr(&Bs[buf][ksb * 16 + b_krow][wn + b_ncol]));
#pragma unroll
            for (int mt = 0; mt < 4; mt++)
#pragma unroll
                for (int nt = 0; nt < 2; nt++)
                    mma16816h(acc[mt][nt], af[mt], &bf[nt * 2]);
        }
    };

    uint4 A00, A01, A10, A11;
    float4 W00, W01, W10, W11;
    ldg(0, A00, A01, W00, W01);
    sts(0, A00, A01, W00, W01);
    ldg(1, A00, A01, W00, W01);
    __syncthreads();

    const int NCHUNK = KSPL / 32;  // 32
    for (int ch = 0; ch < NCHUNK; ch += 2) {
        if (ch + 2 < NCHUNK) ldg(ch + 2, A10, A11, W10, W11);
        compute(0);
        sts(1, A00, A01, W00, W01);
        __syncthreads();
        if (ch + 3 < NCHUNK) ldg(ch + 3, A00, A01, W00, W01);
        compute(1);
        if (ch + 2 < NCHUNK) sts(0, A10, A11, W10, W11);
        __syncthreads();
    }

    // epilogue: Hp -> fp16, row-major [B][NO]; bias only in split 0
    const int r = lane >> 2, c = (lane & 3) * 2;
#pragma unroll
    for (int mt = 0; mt < 4; mt++)
#pragma unroll
        for (int nt = 0; nt < 2; nt++) {
            int ocol = obase + wn + nt * 8 + c;
            float bv0 = ks ? 0.0f : bias[n * O_DIM + ocol];
            float bv1 = ks ? 0.0f : bias[n * O_DIM + ocol + 1];
            int b0 = bbase + wm + mt * 16 + r;
#pragma unroll
            for (int q = 0; q < 2; q++) {
                size_t base = (size_t)(b0 + q*8) * NO_DIM + (size_t)n * O_DIM + ocol;
                *(uint32_t*)&Hdst[base] =
                    pack2h(acc[mt][nt][q*2] + bv0, acc[mt][nt][q*2+1] + bv1);
            }
        }
}

// ---------------------------------------------------------------- GEMM2 (fp16, BK=16, prefetch-2, occ 2, 37 balanced K-splits)
// split s covers chunk-pairs [9s, 9s+9) for s<32, [8s+32, 8s+40) for s>=32
__global__ __launch_bounds__(256, 2) void gemm2_kernel(const float* __restrict__ W3)
{
    __shared__ alignas(16) unsigned short As[2][128][24];   // 12 KB
    __shared__ alignas(16) unsigned short Bs[2][16][136];   // 8.5 KB

    const int s = blockIdx.z, bbase = blockIdx.x * 128, ebase = blockIdx.y * 128;
    const int pair0  = (s < 32) ? 9 * s : 8 * s + 32;
    const int npairs = (s < 32) ? 9 : 8;
    const int kbeg   = pair0 * 32;
    const int NCHUNK = npairs * 2;            // 18 or 16 (even)

    const int tid = threadIdx.x, lane = tid & 31, warp = tid >> 5;
    const int wm = (warp & 1) * 64, wn = (warp >> 1) * 32;
    const int arow = tid >> 1, ahalf = (tid & 1) * 8;
    const int kkB = tid >> 5, colB = (tid & 31) * 4;
    const int g8 = lane >> 3, i8 = lane & 7;
    const int a_mrow = (g8 & 1) * 8 + i8, a_kcol = (g8 >> 1) * 8;
    const int b_krow = (g8 & 1) * 8 + i8, b_ncol = (g8 >> 1) * 8;

    float acc[4][4][4];
#pragma unroll
    for (int i = 0; i < 4; i++)
#pragma unroll
        for (int j = 0; j < 4; j++)
#pragma unroll
            for (int q = 0; q < 4; q++) acc[i][j][q] = 0.0f;

    auto ldg = [&](int ch, uint4& a0, uint4& a1, float4& p0, float4& p1) {
        int k0 = kbeg + ch * 16;
        size_t off = (size_t)(bbase + arow) * NO_DIM + k0 + ahalf;
        a0 = *(const uint4*)&g_H0[off];
        a1 = *(const uint4*)&g_H1[off];
        p0 = *(const float4*)&W3[(size_t)(k0 + kkB) * E_DIM + ebase + colB];
        p1 = *(const float4*)&W3[(size_t)(k0 + kkB + 8) * E_DIM + ebase + colB];
    };
    auto sts = [&](int buf, uint4 a0, uint4 a1, float4 p0, float4 p1) {
        uint4 c;
        c.x = h2add(a0.x, a1.x); c.y = h2add(a0.y, a1.y);
        c.z = h2add(a0.z, a1.z); c.w = h2add(a0.w, a1.w);
        *(uint4*)&As[buf][arow][ahalf] = c;
        *(uint2*)&Bs[buf][kkB][colB]     = make_uint2(pack2h(p0.x, p0.y), pack2h(p0.z, p0.w));
        *(uint2*)&Bs[buf][kkB + 8][colB] = make_uint2(pack2h(p1.x, p1.y), pack2h(p1.z, p1.w));
    };
    auto compute = [&](int buf) {
        uint32_t af[4][4], bfv[2][4];
#pragma unroll
        for (int mt = 0; mt < 4; mt++)
            ldsm4(af[mt], sptr(&As[buf][wm + mt * 16 + a_mrow][a_kcol]));
#pragma unroll
        for (int np = 0; np < 2; np++)
            ldsm4t(bfv[np], sptr(&Bs[buf][b_krow][wn + np * 16 + b_ncol]));
#pragma unroll
        for (int mt = 0; mt < 4; mt++)
#pragma unroll
            for (int nt = 0; nt < 4; nt++)
                mma16816h(acc[mt][nt], af[mt], &bfv[nt >> 1][(nt & 1) * 2]);
    };

    uint4 Ah0, Al0, Ah1, Al1;
    float4 B00, B01, B10, B11;
    ldg(0, Ah0, Al0, B00, B01);
    sts(0, Ah0, Al0, B00, B01);
    ldg(1, Ah0, Al0, B00, B01);
    __syncthreads();

    for (int ch = 0; ch < NCHUNK; ch += 2) {
        if (ch + 2 < NCHUNK) ldg(ch + 2, Ah1, Al1, B10, B11);
        compute(0);
        sts(1, Ah0, Al0, B00, B01);
        __syncthreads();
        if (ch + 3 < NCHUNK) ldg(ch + 3, Ah0, Al0, B00, B01);
        compute(1);
        if (ch + 2 < NCHUNK) sts(0, Ah1, Al1, B10, B11);
        __syncthreads();
    }

    float* Ps = g_P + (size_t)s * B_DIM * E_DIM;
    const int r = lane >> 2, c = (lane & 3) * 2;
#pragma unroll
    for (int mt = 0; mt < 4; mt++)
#pragma unroll
        for (int nt = 0; nt < 4; nt++) {
            int ecol = ebase + wn + nt * 8 + c;
            int b0 = bbase + wm + mt * 16 + r;
            *(float2*)&Ps[(size_t)b0 * E_DIM + ecol] = make_float2(acc[mt][nt][0], acc[mt][nt][1]);
            *(float2*)&Ps[(size_t)(b0 + 8) * E_DIM + ecol] = make_float2(acc[mt][nt][2], acc[mt][nt][3]);
        }
}

// ---------------------------------------------------------------- reduce (scalar, 512 blocks, 4 accumulators, L1-bypass)
__global__ __launch_bounds__(256) void reduce_kernel(const float* __restrict__ b3, float* __restrict__ out) {
    int i = blockIdx.x * 256 + threadIdx.x;     // 0..131071
    int e = i & (E_DIM - 1);
    const size_t BE = (size_t)B_DIM * E_DIM;
    float s0 = b3[e], s1 = 0.0f, s2 = 0.0f, s3 = 0.0f;
#pragma unroll
    for (int s = 0; s + 4 <= NSPL2; s += 4) {
        s0 += __ldcg(&g_P[(size_t)(s + 0) * BE + i]);
        s1 += __ldcg(&g_P[(size_t)(s + 1) * BE + i]);
        s2 += __ldcg(&g_P[(size_t)(s + 2) * BE + i]);
        s3 += __ldcg(&g_P[(size_t)(s + 3) * BE + i]);
    }
    s0 += __ldcg(&g_P[(size_t)(NSPL2 - 1) * BE + i]);   // 37 = 9*4 + 1
    float sum = (s0 + s1) + (s2 + s3);
    out[i] = (sum >= 0.f) ? sum : NEG_SLOPE * sum;
}

// ----------------------------------------------------------------
extern "C" void kernel_launch(void* const* d_in, const int* in_sizes, int n_in,
                              void* d_out, int out_size) {
    const float* x    = (const float*)d_in[0];
    const int*   gidx = (const int*)  d_in[1];
    const float* W    = (const float*)d_in[2];
    const float* bias = (const float*)d_in[3];
    const float* W3   = (const float*)d_in[4];
    const float* b3   = (const float*)d_in[5];
    float* out = (float*)d_out;

    {
        dim3 grid(D_DIM / 64, B_DIM / 64);
        transpose_kernel<<<grid, 256>>>(x);
    }
    {
        dim3 grid(B_DIM / 128, O_DIM / 64, N_DIM * 2);   // (2,4,82) = 656 CTAs
        gemm1_kernel<<<grid, 256>>>(gidx, W, bias);
    }
    {
        dim3 grid(B_DIM / 128, E_DIM / 128, NSPL2);      // (2,4,37) = 296 CTAs = 1 wave
        gemm2_kernel<<<grid, 256>>>(W3);
    }
    {
        reduce_kernel<<<(B_DIM * E_DIM) / 256, 256>>>(b3, out);   // 512 blocks
    }
}